// round 4
// baseline (speedup 1.0000x reference)
#include <cuda_runtime.h>

// ROIAlign: features (4, 64, 38, 38) fp32, rois (4, 2904, 4) -> (11616, 64, 7, 7).
//
// R4: same NHWC-gather + smem-staged-store structure as R3, but persistent
// software-pipelined blocks:
//   - 740 blocks loop over (roi, half) work items
//   - next item's bilinear weights computed while current item's gathers are
//     in flight (double-buffered weight smem)
//   - flush stores of item i overlap gathers of item i+1

#define FB 4
#define FH 38
#define FW 38
#define FC 64
#define OS 7
#define PLANE (FH * FW)               // 1444
#define PER_ROI (FC * OS * OS)        // 3136
#define HALF_CH 32
#define HALF_OUT (HALF_CH * OS * OS)  // 1568
#define NPIX (OS * OS)                // 49

__device__ float g_nhwc[FB * PLANE * FC];   // [b][h][w][c], 1.48 MB

// ---------------- kernel 1: NCHW -> NHWC tiled transpose ----------------
__global__ __launch_bounds__(256)
void nchw2nhwc_kernel(const float* __restrict__ feat)
{
    __shared__ float tile[32][33];
    const int b = blockIdx.z;
    const int hw0 = blockIdx.x * 32;
    const int c0 = blockIdx.y * 32;

    const float* in = feat + (size_t)b * FC * PLANE;
    float* outp = g_nhwc + (size_t)b * PLANE * FC;

    const int tx = threadIdx.x;
    const int ty = threadIdx.y;

#pragma unroll
    for (int i = 0; i < 32; i += 8) {
        const int c = c0 + ty + i;
        const int hw = hw0 + tx;
        if (hw < PLANE)
            tile[ty + i][tx] = in[c * PLANE + hw];
    }
    __syncthreads();
#pragma unroll
    for (int i = 0; i < 32; i += 8) {
        const int hw = hw0 + ty + i;
        const int c = c0 + tx;
        if (hw < PLANE)
            outp[hw * FC + c] = tile[tx][ty + i];
    }
}

// weight/offset computation for pixel q of roi n (one thread per pixel)
__device__ __forceinline__ void compute_wo(const float* __restrict__ rois,
                                           int n, int q,
                                           float4* __restrict__ swb,
                                           int4* __restrict__ sob)
{
    const float4 r = __ldg(reinterpret_cast<const float4*>(rois) + n);
    const float rw = fmaxf(r.z - r.x, 1.0f);
    const float rh = fmaxf(r.w - r.y, 1.0f);

    const int ox = q % OS;
    const int oy = q / OS;

    const float x = fmaf((float)ox * (1.0f / 6.0f), rw, r.x);
    const float y = fmaf((float)oy * (1.0f / 6.0f), rh, r.y);

    const float x0f = floorf(x);
    const float y0f = floorf(y);
    const float fx = x - x0f;
    const float fy = y - y0f;

    const int x0 = (int)x0f, y0 = (int)y0f;
    const int x1 = x0 + 1, y1 = y0 + 1;

    const bool vx0 = (x0 >= 0) && (x0 <= FW - 1);
    const bool vx1 = (x1 >= 0) && (x1 <= FW - 1);
    const bool vy0 = (y0 >= 0) && (y0 <= FH - 1);
    const bool vy1 = (y1 >= 0) && (y1 <= FH - 1);

    const int xi0 = min(max(x0, 0), FW - 1);
    const int xi1 = min(max(x1, 0), FW - 1);
    const int yi0 = min(max(y0, 0), FH - 1);
    const int yi1 = min(max(y1, 0), FH - 1);

    const float wx0 = 1.0f - fx, wx1 = fx;
    const float wy0 = 1.0f - fy, wy1 = fy;

    float4 w;
    w.x = (vx0 && vy0) ? wx0 * wy0 : 0.0f;
    w.y = (vx1 && vy0) ? wx1 * wy0 : 0.0f;
    w.z = (vx0 && vy1) ? wx0 * wy1 : 0.0f;
    w.w = (vx1 && vy1) ? wx1 * wy1 : 0.0f;
    swb[q] = w;

    int4 o;
    o.x = (yi0 * FW + xi0) * FC;
    o.y = (yi0 * FW + xi1) * FC;
    o.z = (yi1 * FW + xi0) * FC;
    o.w = (yi1 * FW + xi1) * FC;
    sob[q] = o;
}

// ---------------- kernel 2: persistent pipelined ROIAlign ----------------
// work item = (roi, half). blockDim = (8, 49) = 392 threads.
//   threadIdx.x = cg in [0,8): 4 channels (float4) at 32*half + 4*cg
//   threadIdx.y = p in [0,49): output pixel
__global__ __launch_bounds__(392, 5)
void roialign_nhwc_kernel(const float* __restrict__ rois,
                          float* __restrict__ out,
                          int n_items, int nb_per_batch)
{
    __shared__ float4 sw[2][NPIX];
    __shared__ int4   so[2][NPIX];
    __shared__ float  s[HALF_OUT];       // staging: [c_local*49 + p]

    const int cg = threadIdx.x;          // 0..7
    const int p = threadIdx.y;           // 0..48
    const int tid = cg + 8 * p;          // 0..391
    const int step = gridDim.x;

    int item = blockIdx.x;
    if (item >= n_items) return;         // uniform per block

    if (tid < NPIX)
        compute_wo(rois, item >> 1, tid, sw[0], so[0]);
    __syncthreads();

    int buf = 0;
    for (; item < n_items; item += step) {
        const float4 w = sw[buf][p];
        const int4 o = so[buf][p];

        const int n = item >> 1;
        const int half = item & 1;
        const int b = n / nb_per_batch;

        const float* __restrict__ fb =
            g_nhwc + (size_t)b * PLANE * FC + HALF_CH * half + 4 * cg;

        const float4 v00 = *reinterpret_cast<const float4*>(fb + o.x);
        const float4 v01 = *reinterpret_cast<const float4*>(fb + o.y);
        const float4 v10 = *reinterpret_cast<const float4*>(fb + o.z);
        const float4 v11 = *reinterpret_cast<const float4*>(fb + o.w);

        // overlap: compute next item's weights while gathers are in flight
        const int nxt = item + step;
        if (tid < NPIX && nxt < n_items)
            compute_wo(rois, nxt >> 1, tid, sw[buf ^ 1], so[buf ^ 1]);

        float4 a;
        a.x = fmaf(w.x, v00.x, fmaf(w.y, v01.x, fmaf(w.z, v10.x, w.w * v11.x)));
        a.y = fmaf(w.x, v00.y, fmaf(w.y, v01.y, fmaf(w.z, v10.y, w.w * v11.y)));
        a.z = fmaf(w.x, v00.z, fmaf(w.y, v01.z, fmaf(w.z, v10.z, w.w * v11.z)));
        a.w = fmaf(w.x, v00.w, fmaf(w.y, v01.w, fmaf(w.z, v10.w, w.w * v11.w)));

        // barrier: (a) prev flush finished reading s, (b) next weights ready
        __syncthreads();

        const int cl = 4 * cg;           // local channel 0..31
        s[(cl + 0) * NPIX + p] = a.x;    // conflict-free (banks all distinct)
        s[(cl + 1) * NPIX + p] = a.y;
        s[(cl + 2) * NPIX + p] = a.z;
        s[(cl + 3) * NPIX + p] = a.w;

        __syncthreads();

        // flush: 392 coalesced float4 stores (overlaps next iter's gathers)
        float4* o4 = reinterpret_cast<float4*>(
            out + (size_t)n * PER_ROI + half * HALF_OUT);
        o4[tid] = reinterpret_cast<const float4*>(s)[tid];

        buf ^= 1;
    }
}

extern "C" void kernel_launch(void* const* d_in, const int* in_sizes, int n_in,
                              void* d_out, int out_size)
{
    const float* feat = (const float*)d_in[0];   // (B, 64, 38, 38)
    const float* rois = (const float*)d_in[1];   // (B, Nb, 4)
    float* out = (float*)d_out;

    const int B = in_sizes[0] / (FC * PLANE);    // 4
    const int n_roi = in_sizes[1] / 4;           // 11616
    const int nb = n_roi / B;                    // 2904

    dim3 tgrid((PLANE + 31) / 32, FC / 32, B);
    dim3 tblock(32, 8);
    nchw2nhwc_kernel<<<tgrid, tblock>>>(feat);

    const int n_items = n_roi * 2;
    const int nblocks = 148 * 5;                 // persistent: 5 blocks/SM
    dim3 block(8, 49);
    roialign_nhwc_kernel<<<nblocks, block>>>(rois, out, n_items, nb);
}

// round 5
// speedup vs baseline: 1.1072x; 1.1072x over previous
#include <cuda_runtime.h>

// ROIAlign: features (4, 64, 38, 38) fp32, rois (4, 2904, 4) -> (11616, 64, 7, 7).
//
// R5: NHWC gathers with NO smem staging, NO barriers.
// Thread = (one output pixel) x (8 channels, split as c=4cg..4cg+3 and
// c+32). Warp = 8 channel-groups x 4 consecutive global pixels:
//   - each gather LDG.128 instruction covers 4 runs of 128B contiguous
//     (8 cg x 16B) -> 16 sectors = minimum
//   - stores are 8 scalar STG.32 (8 x 16B runs/inst = 2x min, cheap: stores
//     are 1/4 of gather bytes)
//   - bilinear weights computed once per thread, reused for 8 channels

#define FB 4
#define FH 38
#define FW 38
#define FC 64
#define OS 7
#define PLANE (FH * FW)               // 1444
#define PER_ROI (FC * OS * OS)        // 3136
#define NPIX (OS * OS)                // 49

__device__ float g_nhwc[FB * PLANE * FC];   // [b][h][w][c], 1.48 MB

// ---------------- kernel 1: NCHW -> NHWC tiled transpose ----------------
__global__ __launch_bounds__(256)
void nchw2nhwc_kernel(const float* __restrict__ feat)
{
    __shared__ float tile[32][33];
    const int b = blockIdx.z;
    const int hw0 = blockIdx.x * 32;
    const int c0 = blockIdx.y * 32;

    const float* in = feat + (size_t)b * FC * PLANE;
    float* outp = g_nhwc + (size_t)b * PLANE * FC;

    const int tx = threadIdx.x;
    const int ty = threadIdx.y;

#pragma unroll
    for (int i = 0; i < 32; i += 8) {
        const int c = c0 + ty + i;
        const int hw = hw0 + tx;
        if (hw < PLANE)
            tile[ty + i][tx] = in[c * PLANE + hw];
    }
    __syncthreads();
#pragma unroll
    for (int i = 0; i < 32; i += 8) {
        const int hw = hw0 + ty + i;
        const int c = c0 + tx;
        if (hw < PLANE)
            outp[hw * FC + c] = tile[tx][ty + i];
    }
}

// ---------------- kernel 2: ROIAlign, direct ----------------
// 256 threads/block. tid = cg + 8*pslot; global pixel item = blk*32 + pslot.
__global__ __launch_bounds__(256)
void roialign_nhwc_kernel(const float* __restrict__ rois,
                          float* __restrict__ out,
                          int nb_per_batch)
{
    const int tid = threadIdx.x;
    const int cg = tid & 7;                       // 0..7
    const int pslot = tid >> 3;                   // 0..31
    const int p_item = blockIdx.x * 32 + pslot;   // global (roi,pixel) index

    const int n = p_item / NPIX;                  // roi index
    const int p = p_item - n * NPIX;              // pixel 0..48
    const int b = n / nb_per_batch;

    // ---- bilinear weights/offsets for this pixel ----
    const float4 r = __ldg(reinterpret_cast<const float4*>(rois) + n);
    const float rw = fmaxf(r.z - r.x, 1.0f);
    const float rh = fmaxf(r.w - r.y, 1.0f);

    const int ox = p % OS;
    const int oy = p / OS;

    const float x = fmaf((float)ox * (1.0f / 6.0f), rw, r.x);
    const float y = fmaf((float)oy * (1.0f / 6.0f), rh, r.y);

    const float x0f = floorf(x);
    const float y0f = floorf(y);
    const float fx = x - x0f;
    const float fy = y - y0f;

    const int x0 = (int)x0f, y0 = (int)y0f;
    const int x1 = x0 + 1, y1 = y0 + 1;

    const bool vx0 = (x0 >= 0) && (x0 <= FW - 1);
    const bool vx1 = (x1 >= 0) && (x1 <= FW - 1);
    const bool vy0 = (y0 >= 0) && (y0 <= FH - 1);
    const bool vy1 = (y1 >= 0) && (y1 <= FH - 1);

    const int xi0 = min(max(x0, 0), FW - 1);
    const int xi1 = min(max(x1, 0), FW - 1);
    const int yi0 = min(max(y0, 0), FH - 1);
    const int yi1 = min(max(y1, 0), FH - 1);

    const float wx0 = 1.0f - fx, wx1 = fx;
    const float wy0 = 1.0f - fy, wy1 = fy;

    const float w00 = (vx0 && vy0) ? wx0 * wy0 : 0.0f;
    const float w01 = (vx1 && vy0) ? wx1 * wy0 : 0.0f;
    const float w10 = (vx0 && vy1) ? wx0 * wy1 : 0.0f;
    const float w11 = (vx1 && vy1) ? wx1 * wy1 : 0.0f;

    const int o00 = (yi0 * FW + xi0) * FC;
    const int o01 = (yi0 * FW + xi1) * FC;
    const int o10 = (yi1 * FW + xi0) * FC;
    const int o11 = (yi1 * FW + xi1) * FC;

    // ---- gather: channels [4cg,4cg+4) and [4cg+32,4cg+36) ----
    const float* __restrict__ fb = g_nhwc + (size_t)b * PLANE * FC + 4 * cg;

    float4 aL, aH;
    {
        const float4 lo = *reinterpret_cast<const float4*>(fb + o00);
        const float4 hi = *reinterpret_cast<const float4*>(fb + o00 + 32);
        aL.x = w00 * lo.x; aL.y = w00 * lo.y; aL.z = w00 * lo.z; aL.w = w00 * lo.w;
        aH.x = w00 * hi.x; aH.y = w00 * hi.y; aH.z = w00 * hi.z; aH.w = w00 * hi.w;
    }
    {
        const float4 lo = *reinterpret_cast<const float4*>(fb + o01);
        const float4 hi = *reinterpret_cast<const float4*>(fb + o01 + 32);
        aL.x = fmaf(w01, lo.x, aL.x); aL.y = fmaf(w01, lo.y, aL.y);
        aL.z = fmaf(w01, lo.z, aL.z); aL.w = fmaf(w01, lo.w, aL.w);
        aH.x = fmaf(w01, hi.x, aH.x); aH.y = fmaf(w01, hi.y, aH.y);
        aH.z = fmaf(w01, hi.z, aH.z); aH.w = fmaf(w01, hi.w, aH.w);
    }
    {
        const float4 lo = *reinterpret_cast<const float4*>(fb + o10);
        const float4 hi = *reinterpret_cast<const float4*>(fb + o10 + 32);
        aL.x = fmaf(w10, lo.x, aL.x); aL.y = fmaf(w10, lo.y, aL.y);
        aL.z = fmaf(w10, lo.z, aL.z); aL.w = fmaf(w10, lo.w, aL.w);
        aH.x = fmaf(w10, hi.x, aH.x); aH.y = fmaf(w10, hi.y, aH.y);
        aH.z = fmaf(w10, hi.z, aH.z); aH.w = fmaf(w10, hi.w, aH.w);
    }
    {
        const float4 lo = *reinterpret_cast<const float4*>(fb + o11);
        const float4 hi = *reinterpret_cast<const float4*>(fb + o11 + 32);
        aL.x = fmaf(w11, lo.x, aL.x); aL.y = fmaf(w11, lo.y, aL.y);
        aL.z = fmaf(w11, lo.z, aL.z); aL.w = fmaf(w11, lo.w, aL.w);
        aH.x = fmaf(w11, hi.x, aH.x); aH.y = fmaf(w11, hi.y, aH.y);
        aH.z = fmaf(w11, hi.z, aH.z); aH.w = fmaf(w11, hi.w, aH.w);
    }

    // ---- store: out[n][c][p], c = 4cg+j and 4cg+32+j ----
    float* __restrict__ ob = out + (size_t)n * PER_ROI + 4 * cg * NPIX + p;
    ob[0 * NPIX] = aL.x;
    ob[1 * NPIX] = aL.y;
    ob[2 * NPIX] = aL.z;
    ob[3 * NPIX] = aL.w;
    ob[32 * NPIX + 0 * NPIX] = aH.x;
    ob[32 * NPIX + 1 * NPIX] = aH.y;
    ob[32 * NPIX + 2 * NPIX] = aH.z;
    ob[32 * NPIX + 3 * NPIX] = aH.w;
}

extern "C" void kernel_launch(void* const* d_in, const int* in_sizes, int n_in,
                              void* d_out, int out_size)
{
    const float* feat = (const float*)d_in[0];   // (B, 64, 38, 38)
    const float* rois = (const float*)d_in[1];   // (B, Nb, 4)
    float* out = (float*)d_out;

    const int B = in_sizes[0] / (FC * PLANE);    // 4
    const int n_roi = in_sizes[1] / 4;           // 11616
    const int nb = n_roi / B;                    // 2904

    dim3 tgrid((PLANE + 31) / 32, FC / 32, B);
    dim3 tblock(32, 8);
    nchw2nhwc_kernel<<<tgrid, tblock>>>(feat);

    const int n_items = n_roi * NPIX;            // 569184 (divisible by 32)
    roialign_nhwc_kernel<<<n_items / 32, 256>>>(rois, out, nb);
}

// round 6
// speedup vs baseline: 1.2507x; 1.1297x over previous
#include <cuda_runtime.h>

// ROIAlign: features (4, 64, 38, 38) fp32, rois (4, 2904, 4) -> (11616, 64, 7, 7).
//
// R6: NHWC gathers (optimal 128B-run LDG.128) + smem-staged coalesced float4
// output stores, with exposure minimized:
//   - per-thread bilinear weights (no 49-thread serial phase, no barrier #1)
//   - exactly ONE __syncthreads per block (STS -> flush)
//   - conflict-free STS banking; float4 LDS + coalesced STG.128 flush
// Block = (8 cg, 49 px) = 392 threads, handles half a ROI (32 channels).

#define FB 4
#define FH 38
#define FW 38
#define FC 64
#define OS 7
#define PLANE (FH * FW)               // 1444
#define PER_ROI (FC * OS * OS)        // 3136
#define HALF_CH 32
#define HALF_OUT (HALF_CH * OS * OS)  // 1568
#define NPIX (OS * OS)                // 49

__device__ float g_nhwc[FB * PLANE * FC];   // [b][h][w][c], 1.48 MB

// ---------------- kernel 1: NCHW -> NHWC tiled transpose ----------------
__global__ __launch_bounds__(256)
void nchw2nhwc_kernel(const float* __restrict__ feat)
{
    __shared__ float tile[32][33];
    const int b = blockIdx.z;
    const int hw0 = blockIdx.x * 32;
    const int c0 = blockIdx.y * 32;

    const float* in = feat + (size_t)b * FC * PLANE;
    float* outp = g_nhwc + (size_t)b * PLANE * FC;

    const int tx = threadIdx.x;
    const int ty = threadIdx.y;

#pragma unroll
    for (int i = 0; i < 32; i += 8) {
        const int c = c0 + ty + i;
        const int hw = hw0 + tx;
        if (hw < PLANE)
            tile[ty + i][tx] = in[c * PLANE + hw];
    }
    __syncthreads();
#pragma unroll
    for (int i = 0; i < 32; i += 8) {
        const int hw = hw0 + ty + i;
        const int c = c0 + tx;
        if (hw < PLANE)
            outp[hw * FC + c] = tile[tx][ty + i];
    }
}

// ---------------- kernel 2: ROIAlign, single-barrier staged ----------------
// grid = (n_roi, 2). blockDim = (8, 49) = 392 threads.
//   blockIdx.y = half: channels [32*half, 32*half+32)
//   threadIdx.x = cg in [0,8): 4 channels (float4) at 32*half + 4*cg
//   threadIdx.y = p in [0,49): output pixel (weights computed per-thread)
__global__ __launch_bounds__(392, 5)
void roialign_nhwc_kernel(const float* __restrict__ rois,
                          float* __restrict__ out,
                          int nb_per_batch)
{
    __shared__ float s[HALF_OUT];        // staging: [c_local*49 + p], 6.3 KB

    const int n = blockIdx.x;
    const int half = blockIdx.y;
    const int cg = threadIdx.x;          // 0..7
    const int p = threadIdx.y;           // 0..48
    const int tid = cg + 8 * p;          // 0..391
    const int b = n / nb_per_batch;

    // ---- bilinear weights/offsets for this thread's pixel ----
    const float4 r = __ldg(reinterpret_cast<const float4*>(rois) + n);
    const float rw = fmaxf(r.z - r.x, 1.0f);
    const float rh = fmaxf(r.w - r.y, 1.0f);

    const int ox = p % OS;
    const int oy = p / OS;

    const float x = fmaf((float)ox * (1.0f / 6.0f), rw, r.x);
    const float y = fmaf((float)oy * (1.0f / 6.0f), rh, r.y);

    const float x0f = floorf(x);
    const float y0f = floorf(y);
    const float fx = x - x0f;
    const float fy = y - y0f;

    const int x0 = (int)x0f, y0 = (int)y0f;
    const int x1 = x0 + 1, y1 = y0 + 1;

    const bool vx0 = (x0 >= 0) && (x0 <= FW - 1);
    const bool vx1 = (x1 >= 0) && (x1 <= FW - 1);
    const bool vy0 = (y0 >= 0) && (y0 <= FH - 1);
    const bool vy1 = (y1 >= 0) && (y1 <= FH - 1);

    const int xi0 = min(max(x0, 0), FW - 1);
    const int xi1 = min(max(x1, 0), FW - 1);
    const int yi0 = min(max(y0, 0), FH - 1);
    const int yi1 = min(max(y1, 0), FH - 1);

    const float wx0 = 1.0f - fx, wx1 = fx;
    const float wy0 = 1.0f - fy, wy1 = fy;

    const float w00 = (vx0 && vy0) ? wx0 * wy0 : 0.0f;
    const float w01 = (vx1 && vy0) ? wx1 * wy0 : 0.0f;
    const float w10 = (vx0 && vy1) ? wx0 * wy1 : 0.0f;
    const float w11 = (vx1 && vy1) ? wx1 * wy1 : 0.0f;

    const int o00 = (yi0 * FW + xi0) * FC;
    const int o01 = (yi0 * FW + xi1) * FC;
    const int o10 = (yi1 * FW + xi0) * FC;
    const int o11 = (yi1 * FW + xi1) * FC;

    // ---- gather (coalesced 128B runs across cg) + blend ----
    const float* __restrict__ fb =
        g_nhwc + (size_t)b * PLANE * FC + HALF_CH * half + 4 * cg;

    const float4 v00 = *reinterpret_cast<const float4*>(fb + o00);
    const float4 v01 = *reinterpret_cast<const float4*>(fb + o01);
    const float4 v10 = *reinterpret_cast<const float4*>(fb + o10);
    const float4 v11 = *reinterpret_cast<const float4*>(fb + o11);

    float4 a;
    a.x = fmaf(w00, v00.x, fmaf(w01, v01.x, fmaf(w10, v10.x, w11 * v11.x)));
    a.y = fmaf(w00, v00.y, fmaf(w01, v01.y, fmaf(w10, v10.y, w11 * v11.y)));
    a.z = fmaf(w00, v00.z, fmaf(w01, v01.z, fmaf(w10, v10.z, w11 * v11.z)));
    a.w = fmaf(w00, v00.w, fmaf(w01, v01.w, fmaf(w10, v10.w, w11 * v11.w)));

    // ---- stage: conflict-free STS (banks (4cg+17j+p) mod 32 all distinct) ----
    const int cl = 4 * cg;               // local channel 0..31
    s[(cl + 0) * NPIX + p] = a.x;
    s[(cl + 1) * NPIX + p] = a.y;
    s[(cl + 2) * NPIX + p] = a.z;
    s[(cl + 3) * NPIX + p] = a.w;

    __syncthreads();                     // the ONLY barrier

    // ---- flush: 392 coalesced float4 stores ----
    float4* o4 = reinterpret_cast<float4*>(
        out + (size_t)n * PER_ROI + half * HALF_OUT);
    o4[tid] = reinterpret_cast<const float4*>(s)[tid];
}

extern "C" void kernel_launch(void* const* d_in, const int* in_sizes, int n_in,
                              void* d_out, int out_size)
{
    const float* feat = (const float*)d_in[0];   // (B, 64, 38, 38)
    const float* rois = (const float*)d_in[1];   // (B, Nb, 4)
    float* out = (float*)d_out;

    const int B = in_sizes[0] / (FC * PLANE);    // 4
    const int n_roi = in_sizes[1] / 4;           // 11616
    const int nb = n_roi / B;                    // 2904

    dim3 tgrid((PLANE + 31) / 32, FC / 32, B);
    dim3 tblock(32, 8);
    nchw2nhwc_kernel<<<tgrid, tblock>>>(feat);

    dim3 grid(n_roi, 2);
    dim3 block(8, 49);
    roialign_nhwc_kernel<<<grid, block>>>(rois, out, nb);
}